// round 2
// baseline (speedup 1.0000x reference)
#include <cuda_runtime.h>
#include <math.h>

#define HH 384
#define CC 192
#define WSZ 8
#define SHIFTV 4
#define NHEADS 6
#define HDIM 32
#define NTOK 64
#define NWIN 2304
#define TT 147456

// -------- scratch (device globals: no runtime allocation allowed) --------
__device__ float g_q[NWIN*NHEADS*NTOK*HDIM];
__device__ float g_k[NWIN*NHEADS*NTOK*HDIM];
__device__ float g_v[NWIN*NHEADS*NTOK*HDIM];
__device__ float g_ctx[TT*CC];     // attention output, window-token order
__device__ float g_xattn[TT*CC];   // after proj, image-token order
__device__ float g_h[TT*CC];       // shortcut + LN1(attn)
__device__ float g_mid[TT*2*CC];   // gelu(fc1)
__device__ float g_mlp[TT*CC];     // fc2 out
__device__ float g_rpb[NHEADS*NTOK*NTOK];
__device__ float g_btab[225*NHEADS];

// -------- CPB MLP: bias table (225 rows -> 6 heads) --------
__device__ __forceinline__ float cpb_coord(float x) {
    x = x / 7.0f * 8.0f;
    float s = (x > 0.f) ? 1.f : ((x < 0.f) ? -1.f : 0.f);
    return s * log2f(fabsf(x) + 1.0f) / log2f(8.0f);
}

__global__ void k_cpb(const float* __restrict__ w1, const float* __restrict__ b1,
                      const float* __restrict__ w2) {
    int row = blockIdx.x;        // 0..224
    int hh = threadIdx.x;        // 0..511
    float t0 = cpb_coord((float)(row / 15) - 7.0f);
    float t1 = cpb_coord((float)(row % 15) - 7.0f);
    float hv = t0 * w1[hh] + t1 * w1[512 + hh] + b1[hh];
    hv = fmaxf(hv, 0.f);
    __shared__ float red[512];
    for (int nh = 0; nh < 6; nh++) {
        red[hh] = hv * w2[hh * 6 + nh];
        __syncthreads();
        for (int s = 256; s > 0; s >>= 1) {
            if (hh < s) red[hh] += red[hh + s];
            __syncthreads();
        }
        if (hh == 0) g_btab[row * 6 + nh] = red[0];
        __syncthreads();
    }
}

__global__ void k_rpb() {
    int idx = blockIdx.x * 256 + threadIdx.x;   // 6*64*64 = 24576
    if (idx >= NHEADS * NTOK * NTOK) return;
    int nh = idx >> 12;
    int ij = idx & 4095;
    int i = ij >> 6, j = ij & 63;
    int ri = i >> 3, ci = i & 7, rj = j >> 3, cj = j & 7;
    int rel = (ri - rj + 7) * 15 + (ci - cj + 7);
    float b = g_btab[rel * 6 + nh];
    g_rpb[idx] = 16.0f / (1.0f + expf(-b));
}

// -------- generic 64x64-tile GEMM with fused gather/scatter epilogues --------
// MODE 0: QKV (gather rolled windows from hidden)   grid (2304, 9)
// MODE 1: proj (in: g_ctx, out: scatter to image)    grid (2304, 3)
// MODE 2: fc1 + gelu (in: g_h, out: g_mid)           grid (2304, 6)
// MODE 3: fc2 (in: g_mid K=384, out: g_mlp)          grid (2304, 3)
template <int MODE>
__global__ void __launch_bounds__(256) k_gemm(
    const float* __restrict__ Xin,
    const float* __restrict__ W0, const float* __restrict__ B0,
    const float* __restrict__ W1,
    const float* __restrict__ W2, const float* __restrict__ B2)
{
    constexpr int KD  = (MODE == 3) ? 384 : 192;
    constexpr int LDW = (MODE == 2) ? 384 : 192;
    __shared__ float xs[64][68];   // [token][k-chunk]
    __shared__ float wsm[64][68];  // [k-chunk][out col]

    int tid = threadIdx.x;
    int tx = tid & 15, ty = tid >> 4;
    int bw = blockIdx.x;
    int cb = blockIdx.y * 64;

    const float* W = W0;
    const float* Bias = B0;
    float* outq = nullptr;
    if (MODE == 0) {
        int wsel = blockIdx.y / 3;
        cb = (blockIdx.y % 3) * 64;
        if (wsel == 0)      { W = W0; Bias = B0;      outq = g_q; }
        else if (wsel == 1) { W = W1; Bias = nullptr; outq = g_k; }
        else                { W = W2; Bias = B2;      outq = g_v; }
    }

    int wr = 0, wc = 0;
    if (MODE == 0 || MODE == 1) { wr = (bw / 48) * 8; wc = (bw % 48) * 8; }

    float acc[4][4];
#pragma unroll
    for (int i = 0; i < 4; i++)
#pragma unroll
        for (int j = 0; j < 4; j++) acc[i][j] = 0.f;

    for (int k0 = 0; k0 < KD; k0 += 64) {
        // ---- load input tile 64 tokens x 64 k ----
#pragma unroll
        for (int it = 0; it < 4; it++) {
            int s = tid + it * 256;
            int n = s >> 4, c4 = s & 15;
            const float* src;
            if (MODE == 0) {
                int r0 = wr + (n >> 3) + SHIFTV; if (r0 >= HH) r0 -= HH;
                int c0 = wc + (n & 7)  + SHIFTV; if (c0 >= HH) c0 -= HH;
                src = Xin + (r0 * HH + c0) * CC + k0 + c4 * 4;
            } else if (MODE == 1) {
                src = g_ctx + (bw * 64 + n) * CC + k0 + c4 * 4;
            } else if (MODE == 2) {
                src = g_h + (bw * 64 + n) * CC + k0 + c4 * 4;
            } else {
                src = g_mid + (bw * 64 + n) * 384 + k0 + c4 * 4;
            }
            float4 v4 = *(const float4*)src;
            *(float4*)&xs[n][c4 * 4] = v4;
        }
        // ---- load weight tile 64 k x 64 cols ----
#pragma unroll
        for (int it = 0; it < 4; it++) {
            int s = tid + it * 256;
            int kk = s >> 4, c4 = s & 15;
            *(float4*)&wsm[kk][c4 * 4] =
                *(const float4*)(W + (k0 + kk) * LDW + cb + c4 * 4);
        }
        __syncthreads();

        int ty4 = ty * 4;
#pragma unroll 16
        for (int kk = 0; kk < 64; kk++) {
            float4 b4 = *(const float4*)&wsm[kk][tx * 4];
            float a0 = xs[ty4 + 0][kk];
            float a1 = xs[ty4 + 1][kk];
            float a2 = xs[ty4 + 2][kk];
            float a3 = xs[ty4 + 3][kk];
            acc[0][0] += a0 * b4.x; acc[0][1] += a0 * b4.y; acc[0][2] += a0 * b4.z; acc[0][3] += a0 * b4.w;
            acc[1][0] += a1 * b4.x; acc[1][1] += a1 * b4.y; acc[1][2] += a1 * b4.z; acc[1][3] += a1 * b4.w;
            acc[2][0] += a2 * b4.x; acc[2][1] += a2 * b4.y; acc[2][2] += a2 * b4.z; acc[2][3] += a2 * b4.w;
            acc[3][0] += a3 * b4.x; acc[3][1] += a3 * b4.y; acc[3][2] += a3 * b4.z; acc[3][3] += a3 * b4.w;
        }
        __syncthreads();
    }

    // ---- epilogue ----
#pragma unroll
    for (int i = 0; i < 4; i++) {
        int n = ty * 4 + i;
#pragma unroll
        for (int j = 0; j < 4; j++) {
            int c = cb + tx * 4 + j;
            float v = acc[i][j];
            if (MODE == 0) {
                if (Bias) v += Bias[c];
                int hd = c >> 5, d = c & 31;
                outq[((bw * 6 + hd) * 64 + n) * 32 + d] = v;
            } else if (MODE == 1) {
                v += Bias[c];
                int r0 = wr + (n >> 3) + SHIFTV; if (r0 >= HH) r0 -= HH;
                int c0 = wc + (n & 7)  + SHIFTV; if (c0 >= HH) c0 -= HH;
                g_xattn[(r0 * HH + c0) * CC + c] = v;
            } else if (MODE == 2) {
                v += Bias[c];
                v = 0.5f * v * (1.0f + erff(v * 0.70710678118654752f));
                g_mid[(bw * 64 + n) * 384 + c] = v;
            } else {
                v += Bias[c];
                g_mlp[(bw * 64 + n) * CC + c] = v;
            }
        }
    }
}

// -------- windowed cosine attention: one block per (window, head) --------
__global__ void __launch_bounds__(256) k_attn(const float* __restrict__ logit_scale) {
    int w = blockIdx.x, hd = blockIdx.y;
    __shared__ float qs[64][36], ks[64][36], vs[64][36];
    __shared__ float qinv[64], kinv[64];
    __shared__ float sc[64][65];
    __shared__ int lab[64];
    __shared__ float sscale;

    int tid = threadIdx.x;
    int base = ((w * 6 + hd) * 64) * 32;
#pragma unroll
    for (int it = 0; it < 2; it++) {
        int s = tid + it * 256;
        int n = s >> 3, c4 = s & 7;
        *(float4*)&qs[n][c4 * 4] = *(const float4*)(g_q + base + n * 32 + c4 * 4);
        *(float4*)&ks[n][c4 * 4] = *(const float4*)(g_k + base + n * 32 + c4 * 4);
        *(float4*)&vs[n][c4 * 4] = *(const float4*)(g_v + base + n * 32 + c4 * 4);
    }
    __syncthreads();

    if (tid < 64) {
        float s2 = 0.f;
#pragma unroll
        for (int d = 0; d < 32; d++) s2 += qs[tid][d] * qs[tid][d];
        qinv[tid] = 1.f / fmaxf(sqrtf(s2), 1e-12f);
    } else if (tid < 128) {
        int n = tid - 64;
        float s2 = 0.f;
#pragma unroll
        for (int d = 0; d < 32; d++) s2 += ks[n][d] * ks[n][d];
        kinv[n] = 1.f / fmaxf(sqrtf(s2), 1e-12f);
    } else if (tid < 192) {
        int n = tid - 128;
        int r = (w / 48) * 8 + (n >> 3);
        int c = (w % 48) * 8 + (n & 7);
        int rr = (r < HH - WSZ) ? 0 : ((r < HH - SHIFTV) ? 1 : 2);
        int rc = (c < HH - WSZ) ? 0 : ((c < HH - SHIFTV) ? 1 : 2);
        lab[n] = rr * 3 + rc;
    } else if (tid == 192) {
        sscale = expf(fminf(logit_scale[hd], logf(100.f)));
    }
    __syncthreads();

    int i = tid >> 2;
    int jb = (tid & 3) * 16;
    float qrow[32];
#pragma unroll
    for (int d = 0; d < 32; d++) qrow[d] = qs[i][d];
    float qi = qinv[i] * sscale;
    int labi = lab[i];

    float mv[16];
#pragma unroll
    for (int jj = 0; jj < 16; jj++) {
        int j = jb + jj;
        float dot = 0.f;
#pragma unroll
        for (int d = 0; d < 32; d += 4) {
            float4 kv = *(const float4*)&ks[j][d];
            dot += qrow[d] * kv.x + qrow[d + 1] * kv.y +
                   qrow[d + 2] * kv.z + qrow[d + 3] * kv.w;
        }
        float sv = dot * qi * kinv[j] + g_rpb[(hd << 12) + (i << 6) + j];
        if (labi != lab[j]) sv -= 200.f;   // 2 * (-100) mask
        mv[jj] = sv;
    }
    // softmax over row i (4 lanes per row)
    float m = -1e30f;
#pragma unroll
    for (int jj = 0; jj < 16; jj++) m = fmaxf(m, mv[jj]);
    m = fmaxf(m, __shfl_xor_sync(0xffffffffu, m, 1));
    m = fmaxf(m, __shfl_xor_sync(0xffffffffu, m, 2));
    float ssum = 0.f;
#pragma unroll
    for (int jj = 0; jj < 16; jj++) { mv[jj] = expf(mv[jj] - m); ssum += mv[jj]; }
    ssum += __shfl_xor_sync(0xffffffffu, ssum, 1);
    ssum += __shfl_xor_sync(0xffffffffu, ssum, 2);
    float rinv = 1.f / ssum;
#pragma unroll
    for (int jj = 0; jj < 16; jj++) sc[i][jb + jj] = mv[jj] * rinv;
    __syncthreads();

    // ctx = P @ V : thread covers row i, 8 of 32 dims
    int db = (tid & 3) * 8;
    float a[8];
#pragma unroll
    for (int d = 0; d < 8; d++) a[d] = 0.f;
    for (int j = 0; j < 64; j++) {
        float p = sc[i][j];
        float4 v0 = *(const float4*)&vs[j][db];
        float4 v1 = *(const float4*)&vs[j][db + 4];
        a[0] += p * v0.x; a[1] += p * v0.y; a[2] += p * v0.z; a[3] += p * v0.w;
        a[4] += p * v1.x; a[5] += p * v1.y; a[6] += p * v1.z; a[7] += p * v1.w;
    }
    float* o = g_ctx + ((w << 6) + i) * CC + (hd << 5) + db;
    *(float4*)&o[0] = make_float4(a[0], a[1], a[2], a[3]);
    *(float4*)&o[4] = make_float4(a[4], a[5], a[6], a[7]);
}

// -------- LayerNorm + residual: one warp per token --------
__global__ void __launch_bounds__(256) k_ln_add(
    const float* __restrict__ xres, const float* __restrict__ xln,
    const float* __restrict__ g, const float* __restrict__ b,
    float* __restrict__ out)
{
    int t = blockIdx.x * 8 + (threadIdx.x >> 5);
    int lane = threadIdx.x & 31;
    const float* row = xln + t * CC;
    float v[6];
    float sum = 0.f;
#pragma unroll
    for (int i = 0; i < 6; i++) { v[i] = row[lane + 32 * i]; sum += v[i]; }
#pragma unroll
    for (int o = 16; o > 0; o >>= 1) sum += __shfl_xor_sync(0xffffffffu, sum, o);
    float mu = sum * (1.0f / CC);
    float vs = 0.f;
#pragma unroll
    for (int i = 0; i < 6; i++) { float d = v[i] - mu; vs += d * d; }
#pragma unroll
    for (int o = 16; o > 0; o >>= 1) vs += __shfl_xor_sync(0xffffffffu, vs, o);
    float inv = rsqrtf(vs * (1.0f / CC) + 1e-5f);
#pragma unroll
    for (int i = 0; i < 6; i++) {
        int ch = lane + 32 * i;
        out[t * CC + ch] = xres[t * CC + ch] + (v[i] - mu) * inv * g[ch] + b[ch];
    }
}

// -------- launch --------
extern "C" void kernel_launch(void* const* d_in, const int* in_sizes, int n_in,
                              void* d_out, int out_size) {
    const float* hidden  = (const float*)d_in[0];
    const float* q_w     = (const float*)d_in[1];
    const float* q_b     = (const float*)d_in[2];
    const float* k_w     = (const float*)d_in[3];
    const float* v_w     = (const float*)d_in[4];
    const float* v_b     = (const float*)d_in[5];
    const float* lscale  = (const float*)d_in[6];
    const float* cpb_w1  = (const float*)d_in[7];
    const float* cpb_b1  = (const float*)d_in[8];
    const float* cpb_w2  = (const float*)d_in[9];
    const float* proj_w  = (const float*)d_in[10];
    const float* proj_b  = (const float*)d_in[11];
    const float* ln1_g   = (const float*)d_in[12];
    const float* ln1_b   = (const float*)d_in[13];
    const float* fc1_w   = (const float*)d_in[14];
    const float* fc1_b   = (const float*)d_in[15];
    const float* fc2_w   = (const float*)d_in[16];
    const float* fc2_b   = (const float*)d_in[17];
    const float* ln2_g   = (const float*)d_in[18];
    const float* ln2_b   = (const float*)d_in[19];
    float* out = (float*)d_out;

    float* gh; float* gxa; float* gmlp;
    cudaGetSymbolAddress((void**)&gh, g_h);
    cudaGetSymbolAddress((void**)&gxa, g_xattn);
    cudaGetSymbolAddress((void**)&gmlp, g_mlp);

    k_cpb<<<225, 512>>>(cpb_w1, cpb_b1, cpb_w2);
    k_rpb<<<(NHEADS * NTOK * NTOK + 255) / 256, 256>>>();
    k_gemm<0><<<dim3(NWIN, 9), 256>>>(hidden, q_w, q_b, k_w, v_w, v_b);
    k_attn<<<dim3(NWIN, NHEADS), 256>>>(lscale);
    k_gemm<1><<<dim3(NWIN, 3), 256>>>(nullptr, proj_w, proj_b, nullptr, nullptr, nullptr);
    k_ln_add<<<TT / 8, 256>>>(hidden, gxa, ln1_g, ln1_b, gh);
    k_gemm<2><<<dim3(NWIN, 6), 256>>>(nullptr, fc1_w, fc1_b, nullptr, nullptr, nullptr);
    k_gemm<3><<<dim3(NWIN, 3), 256>>>(nullptr, fc2_w, fc2_b, nullptr, nullptr, nullptr);
    k_ln_add<<<TT / 8, 256>>>(gh, gmlp, ln2_g, ln2_b, out);
}

// round 4
// speedup vs baseline: 1.7893x; 1.7893x over previous
#include <cuda_runtime.h>
#include <math.h>
#include <cstdint>

#define HH 384
#define CC 192
#define WSZ 8
#define SHIFTV 4
#define NHEADS 6
#define HDIM 32
#define NTOK 64
#define NWIN 2304
#define TT 147456

// -------- scratch (device globals) --------
__device__ float g_q[NWIN*NHEADS*NTOK*HDIM];
__device__ float g_k[NWIN*NHEADS*NTOK*HDIM];
__device__ float g_v[NWIN*NHEADS*NTOK*HDIM];
__device__ float g_ctx[TT*CC];
__device__ float g_xattn[TT*CC];
__device__ float g_h[TT*CC];
__device__ float g_mid[TT*2*CC];
__device__ float g_mlp[TT*CC];
__device__ float g_rpb[NHEADS*NTOK*NTOK];
__device__ float g_btab[225*NHEADS];
// transposed weights [N, K] K-major
__device__ float g_wtq[CC*CC];
__device__ float g_wtk[CC*CC];
__device__ float g_wtv[CC*CC];
__device__ float g_wtp[CC*CC];
__device__ float g_wt1[2*CC*CC];   // [384, 192]
__device__ float g_wt2[CC*2*CC];   // [192, 384]

__device__ __forceinline__ uint32_t f2tf32(float x) {
    uint32_t r;
    asm("cvt.rna.tf32.f32 %0, %1;" : "=r"(r) : "f"(x));
    return r;
}

__device__ __forceinline__ void mma_tf32(float& d0, float& d1, float& d2, float& d3,
                                         uint32_t a0, uint32_t a1, uint32_t a2, uint32_t a3,
                                         uint32_t b0, uint32_t b1) {
    asm volatile(
        "mma.sync.aligned.m16n8k8.row.col.f32.tf32.tf32.f32 "
        "{%0,%1,%2,%3}, {%4,%5,%6,%7}, {%8,%9}, {%0,%1,%2,%3};"
        : "+f"(d0), "+f"(d1), "+f"(d2), "+f"(d3)
        : "r"(a0), "r"(a1), "r"(a2), "r"(a3), "r"(b0), "r"(b1));
}

// ======================= weight transpose =======================
__global__ void k_tr(const float* __restrict__ q, const float* __restrict__ k,
                     const float* __restrict__ v, const float* __restrict__ p,
                     const float* __restrict__ f1, const float* __restrict__ f2) {
    int i = blockIdx.x * 256 + threadIdx.x;
    if (i < 36864)        g_wtq[(i % 192) * 192 + i / 192] = q[i];
    else if (i < 73728)  { int j = i - 36864;  g_wtk[(j % 192) * 192 + j / 192] = k[j]; }
    else if (i < 110592) { int j = i - 73728;  g_wtv[(j % 192) * 192 + j / 192] = v[j]; }
    else if (i < 147456) { int j = i - 110592; g_wtp[(j % 192) * 192 + j / 192] = p[j]; }
    else if (i < 221184) { int j = i - 147456; g_wt1[(j % 384) * 192 + j / 384] = f1[j]; }
    else if (i < 294912) { int j = i - 221184; g_wt2[(j % 192) * 384 + j / 192] = f2[j]; }
}

// ======================= CPB / RPB =======================
__device__ __forceinline__ float cpb_coord(float x) {
    x = x / 7.0f * 8.0f;
    float s = (x > 0.f) ? 1.f : ((x < 0.f) ? -1.f : 0.f);
    return s * log2f(fabsf(x) + 1.0f) / log2f(8.0f);
}
__global__ void k_cpb(const float* __restrict__ w1, const float* __restrict__ b1,
                      const float* __restrict__ w2) {
    int row = blockIdx.x;
    int hh = threadIdx.x;
    float t0 = cpb_coord((float)(row / 15) - 7.0f);
    float t1 = cpb_coord((float)(row % 15) - 7.0f);
    float hv = t0 * w1[hh] + t1 * w1[512 + hh] + b1[hh];
    hv = fmaxf(hv, 0.f);
    __shared__ float red[512];
    for (int nh = 0; nh < 6; nh++) {
        red[hh] = hv * w2[hh * 6 + nh];
        __syncthreads();
        for (int s = 256; s > 0; s >>= 1) {
            if (hh < s) red[hh] += red[hh + s];
            __syncthreads();
        }
        if (hh == 0) g_btab[row * 6 + nh] = red[0];
        __syncthreads();
    }
}
__global__ void k_rpb() {
    int idx = blockIdx.x * 256 + threadIdx.x;
    if (idx >= NHEADS * NTOK * NTOK) return;
    int nh = idx >> 12;
    int ij = idx & 4095;
    int i = ij >> 6, j = ij & 63;
    int rel = ((i >> 3) - (j >> 3) + 7) * 15 + ((i & 7) - (j & 7) + 7);
    float b = g_btab[rel * 6 + nh];
    g_rpb[idx] = 16.0f / (1.0f + expf(-b));
}

// ======================= tf32 mma.sync GEMM =======================
// Block tile 128(M) x 192(N), K chunked by 32, double-buffered smem,
// register prefetch. 8 warps = 2(M) x 4(N); warp tile 64x48.
// MODE 0: QKV  grid(1152, 3=weight)  A gathered from hidden
// MODE 1: proj grid(1152, 1)         A=g_ctx, scatter out to image order
// MODE 2: fc1  grid(1152, 2=N half)  A=g_h, gelu epilogue
// MODE 3: fc2  grid(1152, 1)         A=g_mid (K=384)
#define SA_ROW 36
// smem float offsets
#define OFF_A0 0
#define OFF_A1 (128*SA_ROW)
#define OFF_B0 (2*128*SA_ROW)
#define OFF_B1 (2*128*SA_ROW + 192*SA_ROW)
#define SMEM_FLOATS (2*128*SA_ROW + 2*192*SA_ROW)

template <int MODE>
__global__ void __launch_bounds__(256, 1) k_g(const float* __restrict__ Xin,
                                              const float* __restrict__ bias_q,
                                              const float* __restrict__ bias_v) {
    constexpr int KD  = (MODE == 3) ? 384 : 192;
    constexpr int NKB = KD / 32;

    extern __shared__ float sm[];
    int tid = threadIdx.x;
    int wid = tid >> 5, lane = tid & 31;
    int qr = lane >> 2, qc = lane & 3;
    int tile = blockIdx.x;
    int yb = blockIdx.y;

    const float* Wt;
    const float* bias;
    if (MODE == 0) {
        Wt = (yb == 0) ? g_wtq : ((yb == 1) ? g_wtk : g_wtv);
        bias = (yb == 0) ? bias_q : ((yb == 1) ? nullptr : bias_v);
    } else if (MODE == 1) { Wt = g_wtp; bias = bias_q; }
    else if (MODE == 2)   { Wt = g_wt1; bias = bias_q; }
    else                  { Wt = g_wt2; bias = bias_q; }
    int nrow_base = (MODE == 2) ? yb * 192 : 0;

    const float* Asrc;
    if (MODE == 0) Asrc = Xin;
    else if (MODE == 1) Asrc = g_ctx;
    else if (MODE == 2) Asrc = g_h;
    else Asrc = g_mid;

    // prefetch registers
    float4 ar[4];
    float4 br[6];

    // ---- A source address for (row, kb, kc) ----
    auto a_ptr = [&](int row, int kb, int kc) -> const float* {
        long tau = (long)tile * 128 + row;
        if (MODE == 0) {
            int win = (int)(tau >> 6), n = (int)(tau & 63);
            int r0 = (win / 48) * 8 + (n >> 3) + SHIFTV; if (r0 >= HH) r0 -= HH;
            int c0 = (win % 48) * 8 + (n & 7)  + SHIFTV; if (c0 >= HH) c0 -= HH;
            return Asrc + (long)(r0 * HH + c0) * CC + kb * 32 + kc * 4;
        }
        return Asrc + tau * KD + kb * 32 + kc * 4;
    };

    auto LOADREG = [&](int kb) {
#pragma unroll
        for (int i = 0; i < 4; i++) {
            int idx = tid + i * 256;
            int row = idx >> 3, kc = idx & 7;
            ar[i] = *(const float4*)a_ptr(row, kb, kc);
        }
#pragma unroll
        for (int i = 0; i < 6; i++) {
            int idx = tid + i * 256;
            int row = idx >> 3, kc = idx & 7;
            br[i] = *(const float4*)(Wt + (long)(nrow_base + row) * KD + kb * 32 + kc * 4);
        }
    };
    auto STORE = [&](int stg) {
        float* A = sm + (stg ? OFF_A1 : OFF_A0);
        float* B = sm + (stg ? OFF_B1 : OFF_B0);
#pragma unroll
        for (int i = 0; i < 4; i++) {
            int idx = tid + i * 256;
            int row = idx >> 3, kc = idx & 7;
            float* d = A + row * SA_ROW + kc * 4;
            d[0] = __uint_as_float(f2tf32(ar[i].x));
            d[1] = __uint_as_float(f2tf32(ar[i].y));
            d[2] = __uint_as_float(f2tf32(ar[i].z));
            d[3] = __uint_as_float(f2tf32(ar[i].w));
        }
#pragma unroll
        for (int i = 0; i < 6; i++) {
            int idx = tid + i * 256;
            int row = idx >> 3, kc = idx & 7;
            float* d = B + row * SA_ROW + kc * 4;
            d[0] = __uint_as_float(f2tf32(br[i].x));
            d[1] = __uint_as_float(f2tf32(br[i].y));
            d[2] = __uint_as_float(f2tf32(br[i].z));
            d[3] = __uint_as_float(f2tf32(br[i].w));
        }
    };

    float acc[4][6][4];
#pragma unroll
    for (int mf = 0; mf < 4; mf++)
#pragma unroll
        for (int nf = 0; nf < 6; nf++)
#pragma unroll
            for (int t = 0; t < 4; t++) acc[mf][nf][t] = 0.f;

    int rb = (wid & 1) * 64;
    int nb0 = (wid >> 1) * 48;

    LOADREG(0);
    STORE(0);
    for (int kb = 0; kb < NKB; kb++) {
        if (kb + 1 < NKB) LOADREG(kb + 1);
        __syncthreads();
        const uint32_t* A = (const uint32_t*)(sm + ((kb & 1) ? OFF_A1 : OFF_A0));
        const uint32_t* B = (const uint32_t*)(sm + ((kb & 1) ? OFF_B1 : OFF_B0));
#pragma unroll
        for (int k8 = 0; k8 < 4; k8++) {
            int kof = k8 * 8;
            uint32_t a[4][4];
#pragma unroll
            for (int mf = 0; mf < 4; mf++) {
                int r = rb + mf * 16 + qr;
                a[mf][0] = A[r * SA_ROW + kof + qc];
                a[mf][1] = A[(r + 8) * SA_ROW + kof + qc];
                a[mf][2] = A[r * SA_ROW + kof + qc + 4];
                a[mf][3] = A[(r + 8) * SA_ROW + kof + qc + 4];
            }
#pragma unroll
            for (int nf = 0; nf < 6; nf++) {
                int n = nb0 + nf * 8 + qr;
                uint32_t b0 = B[n * SA_ROW + kof + qc];
                uint32_t b1 = B[n * SA_ROW + kof + qc + 4];
#pragma unroll
                for (int mf = 0; mf < 4; mf++)
                    mma_tf32(acc[mf][nf][0], acc[mf][nf][1], acc[mf][nf][2], acc[mf][nf][3],
                             a[mf][0], a[mf][1], a[mf][2], a[mf][3], b0, b1);
            }
        }
        if (kb + 1 < NKB) STORE((kb + 1) & 1);
    }

    // ---- epilogue ----
#pragma unroll
    for (int mf = 0; mf < 4; mf++) {
        int rloc0 = rb + mf * 16 + qr;
#pragma unroll
        for (int t = 0; t < 2; t++) {
            int rloc = rloc0 + t * 8;
            long tau = (long)tile * 128 + rloc;
            int win = (int)(tau >> 6), n = (int)(tau & 63);
#pragma unroll
            for (int nf = 0; nf < 6; nf++) {
                int cloc = nb0 + nf * 8 + qc * 2;
                float vx = acc[mf][nf][t * 2 + 0];
                float vy = acc[mf][nf][t * 2 + 1];
                if (MODE == 0) {
                    if (bias) { vx += bias[cloc]; vy += bias[cloc + 1]; }
                    int head = cloc >> 5, d = cloc & 31;
                    float* dst = ((yb == 0) ? g_q : ((yb == 1) ? g_k : g_v)) +
                                 (((long)(win * 6 + head) * 64 + n) << 5) + d;
                    *(float2*)dst = make_float2(vx, vy);
                } else if (MODE == 1) {
                    vx += bias[cloc]; vy += bias[cloc + 1];
                    int r0 = (win / 48) * 8 + (n >> 3) + SHIFTV; if (r0 >= HH) r0 -= HH;
                    int c0 = (win % 48) * 8 + (n & 7)  + SHIFTV; if (c0 >= HH) c0 -= HH;
                    float* dst = g_xattn + (long)(r0 * HH + c0) * CC + cloc;
                    *(float2*)dst = make_float2(vx, vy);
                } else if (MODE == 2) {
                    int col = yb * 192 + cloc;
                    vx += bias[col]; vy += bias[col + 1];
                    vx = 0.5f * vx * (1.0f + erff(vx * 0.70710678118654752f));
                    vy = 0.5f * vy * (1.0f + erff(vy * 0.70710678118654752f));
                    float* dst = g_mid + tau * 384 + col;
                    *(float2*)dst = make_float2(vx, vy);
                } else {
                    vx += bias[cloc]; vy += bias[cloc + 1];
                    float* dst = g_mlp + tau * CC + cloc;
                    *(float2*)dst = make_float2(vx, vy);
                }
            }
        }
    }
}

// ======================= attention (unchanged from R2 pass) =======================
__global__ void __launch_bounds__(256) k_attn(const float* __restrict__ logit_scale) {
    int w = blockIdx.x, hd = blockIdx.y;
    __shared__ float qs[64][36], ks[64][36], vs[64][36];
    __shared__ float qinv[64], kinv[64];
    __shared__ float sc[64][65];
    __shared__ int lab[64];
    __shared__ float sscale;

    int tid = threadIdx.x;
    int base = ((w * 6 + hd) * 64) * 32;
#pragma unroll
    for (int it = 0; it < 2; it++) {
        int s = tid + it * 256;
        int n = s >> 3, c4 = s & 7;
        *(float4*)&qs[n][c4 * 4] = *(const float4*)(g_q + base + n * 32 + c4 * 4);
        *(float4*)&ks[n][c4 * 4] = *(const float4*)(g_k + base + n * 32 + c4 * 4);
        *(float4*)&vs[n][c4 * 4] = *(const float4*)(g_v + base + n * 32 + c4 * 4);
    }
    __syncthreads();

    if (tid < 64) {
        float s2 = 0.f;
#pragma unroll
        for (int d = 0; d < 32; d++) s2 += qs[tid][d] * qs[tid][d];
        qinv[tid] = 1.f / fmaxf(sqrtf(s2), 1e-12f);
    } else if (tid < 128) {
        int n = tid - 64;
        float s2 = 0.f;
#pragma unroll
        for (int d = 0; d < 32; d++) s2 += ks[n][d] * ks[n][d];
        kinv[n] = 1.f / fmaxf(sqrtf(s2), 1e-12f);
    } else if (tid < 192) {
        int n = tid - 128;
        int r = (w / 48) * 8 + (n >> 3);
        int c = (w % 48) * 8 + (n & 7);
        int rr = (r < HH - WSZ) ? 0 : ((r < HH - SHIFTV) ? 1 : 2);
        int rc = (c < HH - WSZ) ? 0 : ((c < HH - SHIFTV) ? 1 : 2);
        lab[n] = rr * 3 + rc;
    } else if (tid == 192) {
        sscale = expf(fminf(logit_scale[hd], logf(100.f)));
    }
    __syncthreads();

    int i = tid >> 2;
    int jb = (tid & 3) * 16;
    float qrow[32];
#pragma unroll
    for (int d = 0; d < 32; d++) qrow[d] = qs[i][d];
    float qi = qinv[i] * sscale;
    int labi = lab[i];

    float mv[16];
#pragma unroll
    for (int jj = 0; jj < 16; jj++) {
        int j = jb + jj;
        float dot = 0.f;
#pragma unroll
        for (int d = 0; d < 32; d += 4) {
            float4 kv = *(const float4*)&ks[j][d];
            dot += qrow[d] * kv.x + qrow[d + 1] * kv.y +
                   qrow[d + 2] * kv.z + qrow[d + 3] * kv.w;
        }
        float sv = dot * qi * kinv[j] + g_rpb[(hd << 12) + (i << 6) + j];
        if (labi != lab[j]) sv -= 200.f;
        mv[jj] = sv;
    }
    float m = -1e30f;
#pragma unroll
    for (int jj = 0; jj < 16; jj++) m = fmaxf(m, mv[jj]);
    m = fmaxf(m, __shfl_xor_sync(0xffffffffu, m, 1));
    m = fmaxf(m, __shfl_xor_sync(0xffffffffu, m, 2));
    float ssum = 0.f;
#pragma unroll
    for (int jj = 0; jj < 16; jj++) { mv[jj] = expf(mv[jj] - m); ssum += mv[jj]; }
    ssum += __shfl_xor_sync(0xffffffffu, ssum, 1);
    ssum += __shfl_xor_sync(0xffffffffu, ssum, 2);
    float rinv = 1.f / ssum;
#pragma unroll
    for (int jj = 0; jj < 16; jj++) sc[i][jb + jj] = mv[jj] * rinv;
    __syncthreads();

    int db = (tid & 3) * 8;
    float a[8];
#pragma unroll
    for (int d = 0; d < 8; d++) a[d] = 0.f;
    for (int j = 0; j < 64; j++) {
        float p = sc[i][j];
        float4 v0 = *(const float4*)&vs[j][db];
        float4 v1 = *(const float4*)&vs[j][db + 4];
        a[0] += p * v0.x; a[1] += p * v0.y; a[2] += p * v0.z; a[3] += p * v0.w;
        a[4] += p * v1.x; a[5] += p * v1.y; a[6] += p * v1.z; a[7] += p * v1.w;
    }
    float* o = g_ctx + ((w << 6) + i) * CC + (hd << 5) + db;
    *(float4*)&o[0] = make_float4(a[0], a[1], a[2], a[3]);
    *(float4*)&o[4] = make_float4(a[4], a[5], a[6], a[7]);
}

// ======================= LayerNorm + residual =======================
__global__ void __launch_bounds__(256) k_ln_add(
    const float* __restrict__ xres, const float* __restrict__ xln,
    const float* __restrict__ g, const float* __restrict__ b,
    float* __restrict__ out) {
    int t = blockIdx.x * 8 + (threadIdx.x >> 5);
    int lane = threadIdx.x & 31;
    const float* row = xln + t * CC;
    float v[6];
    float sum = 0.f;
#pragma unroll
    for (int i = 0; i < 6; i++) { v[i] = row[lane + 32 * i]; sum += v[i]; }
#pragma unroll
    for (int o = 16; o > 0; o >>= 1) sum += __shfl_xor_sync(0xffffffffu, sum, o);
    float mu = sum * (1.0f / CC);
    float vs = 0.f;
#pragma unroll
    for (int i = 0; i < 6; i++) { float d = v[i] - mu; vs += d * d; }
#pragma unroll
    for (int o = 16; o > 0; o >>= 1) vs += __shfl_xor_sync(0xffffffffu, vs, o);
    float inv = rsqrtf(vs * (1.0f / CC) + 1e-5f);
#pragma unroll
    for (int i = 0; i < 6; i++) {
        int ch = lane + 32 * i;
        out[t * CC + ch] = xres[t * CC + ch] + (v[i] - mu) * inv * g[ch] + b[ch];
    }
}

// ======================= launch =======================
extern "C" void kernel_launch(void* const* d_in, const int* in_sizes, int n_in,
                              void* d_out, int out_size) {
    const float* hidden = (const float*)d_in[0];
    const float* q_w    = (const float*)d_in[1];
    const float* q_b    = (const float*)d_in[2];
    const float* k_w    = (const float*)d_in[3];
    const float* v_w    = (const float*)d_in[4];
    const float* v_b    = (const float*)d_in[5];
    const float* lscale = (const float*)d_in[6];
    const float* cpb_w1 = (const float*)d_in[7];
    const float* cpb_b1 = (const float*)d_in[8];
    const float* cpb_w2 = (const float*)d_in[9];
    const float* proj_w = (const float*)d_in[10];
    const float* proj_b = (const float*)d_in[11];
    const float* ln1_g  = (const float*)d_in[12];
    const float* ln1_b  = (const float*)d_in[13];
    const float* fc1_w  = (const float*)d_in[14];
    const float* fc1_b  = (const float*)d_in[15];
    const float* fc2_w  = (const float*)d_in[16];
    const float* fc2_b  = (const float*)d_in[17];
    const float* ln2_g  = (const float*)d_in[18];
    const float* ln2_b  = (const float*)d_in[19];
    float* out = (float*)d_out;

    float* gh; float* gxa; float* gmlp;
    cudaGetSymbolAddress((void**)&gh, g_h);
    cudaGetSymbolAddress((void**)&gxa, g_xattn);
    cudaGetSymbolAddress((void**)&gmlp, g_mlp);

    const int SMB = SMEM_FLOATS * 4;   // 92160 bytes
    cudaFuncSetAttribute(k_g<0>, cudaFuncAttributeMaxDynamicSharedMemorySize, SMB);
    cudaFuncSetAttribute(k_g<1>, cudaFuncAttributeMaxDynamicSharedMemorySize, SMB);
    cudaFuncSetAttribute(k_g<2>, cudaFuncAttributeMaxDynamicSharedMemorySize, SMB);
    cudaFuncSetAttribute(k_g<3>, cudaFuncAttributeMaxDynamicSharedMemorySize, SMB);

    k_tr<<<1152, 256>>>(q_w, k_w, v_w, proj_w, fc1_w, fc2_w);
    k_cpb<<<225, 512>>>(cpb_w1, cpb_b1, cpb_w2);
    k_rpb<<<(NHEADS * NTOK * NTOK + 255) / 256, 256>>>();
    k_g<0><<<dim3(1152, 3), 256, SMB>>>(hidden, q_b, v_b);
    k_attn<<<dim3(NWIN, NHEADS), 256>>>(lscale);
    k_g<1><<<dim3(1152, 1), 256, SMB>>>(nullptr, proj_b, nullptr);
    k_ln_add<<<TT / 8, 256>>>(hidden, gxa, ln1_g, ln1_b, gh);
    k_g<2><<<dim3(1152, 2), 256, SMB>>>(nullptr, fc1_b, nullptr);
    k_g<3><<<dim3(1152, 1), 256, SMB>>>(nullptr, fc2_b, nullptr);
    k_ln_add<<<TT / 8, 256>>>(gh, gmlp, ln2_g, ln2_b, out);
}

// round 5
// speedup vs baseline: 3.3457x; 1.8698x over previous
#include <cuda_runtime.h>
#include <math.h>
#include <cstdint>

#define HH 384
#define CC 192
#define WSZ 8
#define SHIFTV 4
#define NHEADS 6
#define HDIM 32
#define NTOK 64
#define NWIN 2304
#define TT 147456

// -------- scratch (device globals) --------
__device__ float g_q[NWIN*NHEADS*NTOK*HDIM];
__device__ float g_k[NWIN*NHEADS*NTOK*HDIM];
__device__ float g_v[NWIN*NHEADS*NTOK*HDIM];
__device__ float g_ctx[TT*CC];
__device__ float g_xattn[TT*CC];
__device__ float g_h[TT*CC];
__device__ float g_mid[TT*2*CC];
__device__ float g_mlp[TT*CC];
__device__ float g_rpb[NHEADS*NTOK*NTOK];
__device__ float g_btab[225*NHEADS];
// transposed weights [N, K] K-major
__device__ float g_wtq[CC*CC];
__device__ float g_wtk[CC*CC];
__device__ float g_wtv[CC*CC];
__device__ float g_wtp[CC*CC];
__device__ float g_wt1[2*CC*CC];   // [384, 192]
__device__ float g_wt2[CC*2*CC];   // [192, 384]

__device__ __forceinline__ uint32_t f2tf32(float x) {
    uint32_t r;
    asm("cvt.rna.tf32.f32 %0, %1;" : "=r"(r) : "f"(x));
    return r;
}
__device__ __forceinline__ void split_tf32(float x, uint32_t& hi, uint32_t& lo) {
    hi = f2tf32(x);
    lo = f2tf32(x - __uint_as_float(hi));
}

__device__ __forceinline__ void mma_tf32(float& d0, float& d1, float& d2, float& d3,
                                         uint32_t a0, uint32_t a1, uint32_t a2, uint32_t a3,
                                         uint32_t b0, uint32_t b1) {
    asm volatile(
        "mma.sync.aligned.m16n8k8.row.col.f32.tf32.tf32.f32 "
        "{%0,%1,%2,%3}, {%4,%5,%6,%7}, {%8,%9}, {%0,%1,%2,%3};"
        : "+f"(d0), "+f"(d1), "+f"(d2), "+f"(d3)
        : "r"(a0), "r"(a1), "r"(a2), "r"(a3), "r"(b0), "r"(b1));
}

// ======================= weight transpose =======================
__global__ void k_tr(const float* __restrict__ q, const float* __restrict__ k,
                     const float* __restrict__ v, const float* __restrict__ p,
                     const float* __restrict__ f1, const float* __restrict__ f2) {
    int i = blockIdx.x * 256 + threadIdx.x;
    if (i < 36864)        g_wtq[(i % 192) * 192 + i / 192] = q[i];
    else if (i < 73728)  { int j = i - 36864;  g_wtk[(j % 192) * 192 + j / 192] = k[j]; }
    else if (i < 110592) { int j = i - 73728;  g_wtv[(j % 192) * 192 + j / 192] = v[j]; }
    else if (i < 147456) { int j = i - 110592; g_wtp[(j % 192) * 192 + j / 192] = p[j]; }
    else if (i < 221184) { int j = i - 147456; g_wt1[(j % 384) * 192 + j / 384] = f1[j]; }
    else if (i < 294912) { int j = i - 221184; g_wt2[(j % 192) * 384 + j / 192] = f2[j]; }
}

// ======================= CPB / RPB =======================
__device__ __forceinline__ float cpb_coord(float x) {
    x = x / 7.0f * 8.0f;
    float s = (x > 0.f) ? 1.f : ((x < 0.f) ? -1.f : 0.f);
    return s * log2f(fabsf(x) + 1.0f) / log2f(8.0f);
}
__global__ void k_cpb(const float* __restrict__ w1, const float* __restrict__ b1,
                      const float* __restrict__ w2) {
    int row = blockIdx.x;
    int hh = threadIdx.x;
    float t0 = cpb_coord((float)(row / 15) - 7.0f);
    float t1 = cpb_coord((float)(row % 15) - 7.0f);
    float hv = t0 * w1[hh] + t1 * w1[512 + hh] + b1[hh];
    hv = fmaxf(hv, 0.f);
    __shared__ float red[512];
    for (int nh = 0; nh < 6; nh++) {
        red[hh] = hv * w2[hh * 6 + nh];
        __syncthreads();
        for (int s = 256; s > 0; s >>= 1) {
            if (hh < s) red[hh] += red[hh + s];
            __syncthreads();
        }
        if (hh == 0) g_btab[row * 6 + nh] = red[0];
        __syncthreads();
    }
}
__global__ void k_rpb() {
    int idx = blockIdx.x * 256 + threadIdx.x;
    if (idx >= NHEADS * NTOK * NTOK) return;
    int nh = idx >> 12;
    int ij = idx & 4095;
    int i = ij >> 6, j = ij & 63;
    int rel = ((i >> 3) - (j >> 3) + 7) * 15 + ((i & 7) - (j & 7) + 7);
    float b = g_btab[rel * 6 + nh];
    g_rpb[idx] = 16.0f / (1.0f + __expf(-b));
}

// ======================= tf32 mma.sync GEMM (unchanged from R4 pass) =======================
#define SA_ROW 36
#define OFF_A0 0
#define OFF_A1 (128*SA_ROW)
#define OFF_B0 (2*128*SA_ROW)
#define OFF_B1 (2*128*SA_ROW + 192*SA_ROW)
#define SMEM_FLOATS (2*128*SA_ROW + 2*192*SA_ROW)

template <int MODE>
__global__ void __launch_bounds__(256, 1) k_g(const float* __restrict__ Xin,
                                              const float* __restrict__ bias_q,
                                              const float* __restrict__ bias_v) {
    constexpr int KD  = (MODE == 3) ? 384 : 192;
    constexpr int NKB = KD / 32;

    extern __shared__ float sm[];
    int tid = threadIdx.x;
    int wid = tid >> 5, lane = tid & 31;
    int qr = lane >> 2, qc = lane & 3;
    int tile = blockIdx.x;
    int yb = blockIdx.y;

    const float* Wt;
    const float* bias;
    if (MODE == 0) {
        Wt = (yb == 0) ? g_wtq : ((yb == 1) ? g_wtk : g_wtv);
        bias = (yb == 0) ? bias_q : ((yb == 1) ? nullptr : bias_v);
    } else if (MODE == 1) { Wt = g_wtp; bias = bias_q; }
    else if (MODE == 2)   { Wt = g_wt1; bias = bias_q; }
    else                  { Wt = g_wt2; bias = bias_q; }
    int nrow_base = (MODE == 2) ? yb * 192 : 0;

    const float* Asrc;
    if (MODE == 0) Asrc = Xin;
    else if (MODE == 1) Asrc = g_ctx;
    else if (MODE == 2) Asrc = g_h;
    else Asrc = g_mid;

    float4 ar[4];
    float4 br[6];

    auto a_ptr = [&](int row, int kb, int kc) -> const float* {
        long tau = (long)tile * 128 + row;
        if (MODE == 0) {
            int win = (int)(tau >> 6), n = (int)(tau & 63);
            int r0 = (win / 48) * 8 + (n >> 3) + SHIFTV; if (r0 >= HH) r0 -= HH;
            int c0 = (win % 48) * 8 + (n & 7)  + SHIFTV; if (c0 >= HH) c0 -= HH;
            return Asrc + (long)(r0 * HH + c0) * CC + kb * 32 + kc * 4;
        }
        return Asrc + tau * KD + kb * 32 + kc * 4;
    };

    auto LOADREG = [&](int kb) {
#pragma unroll
        for (int i = 0; i < 4; i++) {
            int idx = tid + i * 256;
            int row = idx >> 3, kc = idx & 7;
            ar[i] = *(const float4*)a_ptr(row, kb, kc);
        }
#pragma unroll
        for (int i = 0; i < 6; i++) {
            int idx = tid + i * 256;
            int row = idx >> 3, kc = idx & 7;
            br[i] = *(const float4*)(Wt + (long)(nrow_base + row) * KD + kb * 32 + kc * 4);
        }
    };
    auto STORE = [&](int stg) {
        float* A = sm + (stg ? OFF_A1 : OFF_A0);
        float* B = sm + (stg ? OFF_B1 : OFF_B0);
#pragma unroll
        for (int i = 0; i < 4; i++) {
            int idx = tid + i * 256;
            int row = idx >> 3, kc = idx & 7;
            float* d = A + row * SA_ROW + kc * 4;
            d[0] = __uint_as_float(f2tf32(ar[i].x));
            d[1] = __uint_as_float(f2tf32(ar[i].y));
            d[2] = __uint_as_float(f2tf32(ar[i].z));
            d[3] = __uint_as_float(f2tf32(ar[i].w));
        }
#pragma unroll
        for (int i = 0; i < 6; i++) {
            int idx = tid + i * 256;
            int row = idx >> 3, kc = idx & 7;
            float* d = B + row * SA_ROW + kc * 4;
            d[0] = __uint_as_float(f2tf32(br[i].x));
            d[1] = __uint_as_float(f2tf32(br[i].y));
            d[2] = __uint_as_float(f2tf32(br[i].z));
            d[3] = __uint_as_float(f2tf32(br[i].w));
        }
    };

    float acc[4][6][4];
#pragma unroll
    for (int mf = 0; mf < 4; mf++)
#pragma unroll
        for (int nf = 0; nf < 6; nf++)
#pragma unroll
            for (int t = 0; t < 4; t++) acc[mf][nf][t] = 0.f;

    int rb = (wid & 1) * 64;
    int nb0 = (wid >> 1) * 48;

    LOADREG(0);
    STORE(0);
    for (int kb = 0; kb < NKB; kb++) {
        if (kb + 1 < NKB) LOADREG(kb + 1);
        __syncthreads();
        const uint32_t* A = (const uint32_t*)(sm + ((kb & 1) ? OFF_A1 : OFF_A0));
        const uint32_t* B = (const uint32_t*)(sm + ((kb & 1) ? OFF_B1 : OFF_B0));
#pragma unroll
        for (int k8 = 0; k8 < 4; k8++) {
            int kof = k8 * 8;
            uint32_t a[4][4];
#pragma unroll
            for (int mf = 0; mf < 4; mf++) {
                int r = rb + mf * 16 + qr;
                a[mf][0] = A[r * SA_ROW + kof + qc];
                a[mf][1] = A[(r + 8) * SA_ROW + kof + qc];
                a[mf][2] = A[r * SA_ROW + kof + qc + 4];
                a[mf][3] = A[(r + 8) * SA_ROW + kof + qc + 4];
            }
#pragma unroll
            for (int nf = 0; nf < 6; nf++) {
                int n = nb0 + nf * 8 + qr;
                uint32_t b0 = B[n * SA_ROW + kof + qc];
                uint32_t b1 = B[n * SA_ROW + kof + qc + 4];
#pragma unroll
                for (int mf = 0; mf < 4; mf++)
                    mma_tf32(acc[mf][nf][0], acc[mf][nf][1], acc[mf][nf][2], acc[mf][nf][3],
                             a[mf][0], a[mf][1], a[mf][2], a[mf][3], b0, b1);
            }
        }
        if (kb + 1 < NKB) STORE((kb + 1) & 1);
    }

#pragma unroll
    for (int mf = 0; mf < 4; mf++) {
        int rloc0 = rb + mf * 16 + qr;
#pragma unroll
        for (int t = 0; t < 2; t++) {
            int rloc = rloc0 + t * 8;
            long tau = (long)tile * 128 + rloc;
            int win = (int)(tau >> 6), n = (int)(tau & 63);
#pragma unroll
            for (int nf = 0; nf < 6; nf++) {
                int cloc = nb0 + nf * 8 + qc * 2;
                float vx = acc[mf][nf][t * 2 + 0];
                float vy = acc[mf][nf][t * 2 + 1];
                if (MODE == 0) {
                    if (bias) { vx += bias[cloc]; vy += bias[cloc + 1]; }
                    int head = cloc >> 5, d = cloc & 31;
                    float* dst = ((yb == 0) ? g_q : ((yb == 1) ? g_k : g_v)) +
                                 (((long)(win * 6 + head) * 64 + n) << 5) + d;
                    *(float2*)dst = make_float2(vx, vy);
                } else if (MODE == 1) {
                    vx += bias[cloc]; vy += bias[cloc + 1];
                    int r0 = (win / 48) * 8 + (n >> 3) + SHIFTV; if (r0 >= HH) r0 -= HH;
                    int c0 = (win % 48) * 8 + (n & 7)  + SHIFTV; if (c0 >= HH) c0 -= HH;
                    float* dst = g_xattn + (long)(r0 * HH + c0) * CC + cloc;
                    *(float2*)dst = make_float2(vx, vy);
                } else if (MODE == 2) {
                    int col = yb * 192 + cloc;
                    vx += bias[col]; vy += bias[col + 1];
                    vx = 0.5f * vx * (1.0f + erff(vx * 0.70710678118654752f));
                    vy = 0.5f * vy * (1.0f + erff(vy * 0.70710678118654752f));
                    float* dst = g_mid + tau * 384 + col;
                    *(float2*)dst = make_float2(vx, vy);
                } else {
                    vx += bias[cloc]; vy += bias[cloc + 1];
                    float* dst = g_mlp + tau * CC + cloc;
                    *(float2*)dst = make_float2(vx, vy);
                }
            }
        }
    }
}

// ======================= tensor-core attention (split tf32) =======================
// One block per (window, head). 128 threads = 4 warps; warp owns 16 rows.
__global__ void __launch_bounds__(128) k_attn(const float* __restrict__ logit_scale) {
    __shared__ float qs[64][36], ks[64][36], vs[64][36];
    __shared__ float ps[64][68];
    __shared__ float qinv[64], kinv[64];
    __shared__ int lab[64];
    __shared__ float sscale;

    int w = blockIdx.x, hd = blockIdx.y;
    int tid = threadIdx.x;
    int wid = tid >> 5, lane = tid & 31;
    int qr = lane >> 2, qc = lane & 3;
    int m0 = wid * 16;

    long base = ((long)(w * 6 + hd) * 64) * 32;
#pragma unroll
    for (int it = 0; it < 4; it++) {
        int s = tid + it * 128;
        int n = s >> 3, c4 = s & 7;
        *(float4*)&qs[n][c4 * 4] = *(const float4*)(g_q + base + n * 32 + c4 * 4);
        *(float4*)&ks[n][c4 * 4] = *(const float4*)(g_k + base + n * 32 + c4 * 4);
        *(float4*)&vs[n][c4 * 4] = *(const float4*)(g_v + base + n * 32 + c4 * 4);
    }
    if (tid == 0) sscale = __expf(fminf(logit_scale[hd], logf(100.f)));
    __syncthreads();

    if (tid < 64) {
        float s2 = 0.f;
#pragma unroll
        for (int d = 0; d < 32; d++) s2 += qs[tid][d] * qs[tid][d];
        qinv[tid] = 1.f / fmaxf(sqrtf(s2), 1e-12f);
        int r = (w / 48) * 8 + (tid >> 3);
        int c = (w % 48) * 8 + (tid & 7);
        int rr = (r < HH - WSZ) ? 0 : ((r < HH - SHIFTV) ? 1 : 2);
        int rc = (c < HH - WSZ) ? 0 : ((c < HH - SHIFTV) ? 1 : 2);
        lab[tid] = rr * 3 + rc;
    } else {
        int n = tid - 64;
        float s2 = 0.f;
#pragma unroll
        for (int d = 0; d < 32; d++) s2 += ks[n][d] * ks[n][d];
        kinv[n] = 1.f / fmaxf(sqrtf(s2), 1e-12f);
    }
    __syncthreads();

    // ---- scores: S[m0..m0+15][0..63] = (qn @ kn^T), split-tf32, 8 n-tiles ----
    float acc[8][4];
#pragma unroll
    for (int nt = 0; nt < 8; nt++)
#pragma unroll
        for (int t = 0; t < 4; t++) acc[nt][t] = 0.f;

    int i0 = m0 + qr, i1 = m0 + qr + 8;
    float qi0 = qinv[i0], qi1 = qinv[i1];

#pragma unroll
    for (int kt = 0; kt < 4; kt++) {
        int k0 = kt * 8;
        uint32_t ah[4], al[4];
        split_tf32(qs[i0][k0 + qc] * qi0,     ah[0], al[0]);
        split_tf32(qs[i1][k0 + qc] * qi1,     ah[1], al[1]);
        split_tf32(qs[i0][k0 + qc + 4] * qi0, ah[2], al[2]);
        split_tf32(qs[i1][k0 + qc + 4] * qi1, ah[3], al[3]);
#pragma unroll
        for (int nt = 0; nt < 8; nt++) {
            int j = nt * 8 + qr;
            float ki = kinv[j];
            uint32_t bh0, bl0, bh1, bl1;
            split_tf32(ks[j][k0 + qc] * ki,     bh0, bl0);
            split_tf32(ks[j][k0 + qc + 4] * ki, bh1, bl1);
            mma_tf32(acc[nt][0], acc[nt][1], acc[nt][2], acc[nt][3],
                     ah[0], ah[1], ah[2], ah[3], bh0, bh1);
            mma_tf32(acc[nt][0], acc[nt][1], acc[nt][2], acc[nt][3],
                     ah[0], ah[1], ah[2], ah[3], bl0, bl1);
            mma_tf32(acc[nt][0], acc[nt][1], acc[nt][2], acc[nt][3],
                     al[0], al[1], al[2], al[3], bh0, bh1);
        }
    }

    // ---- bias + mask + softmax (rows i0, i1) ----
    float scl = sscale;
    int labi0 = lab[i0], labi1 = lab[i1];
    const float* rpb = g_rpb + (hd << 12);
    float mx0 = -1e30f, mx1 = -1e30f;
#pragma unroll
    for (int nt = 0; nt < 8; nt++) {
#pragma unroll
        for (int e = 0; e < 2; e++) {
            int j = nt * 8 + 2 * qc + e;
            int labj = lab[j];
            float s0 = acc[nt][e] * scl + rpb[(i0 << 6) + j];
            if (labi0 != labj) s0 -= 200.f;
            float s1 = acc[nt][2 + e] * scl + rpb[(i1 << 6) + j];
            if (labi1 != labj) s1 -= 200.f;
            acc[nt][e] = s0; acc[nt][2 + e] = s1;
            mx0 = fmaxf(mx0, s0); mx1 = fmaxf(mx1, s1);
        }
    }
    mx0 = fmaxf(mx0, __shfl_xor_sync(0xffffffffu, mx0, 1));
    mx0 = fmaxf(mx0, __shfl_xor_sync(0xffffffffu, mx0, 2));
    mx1 = fmaxf(mx1, __shfl_xor_sync(0xffffffffu, mx1, 1));
    mx1 = fmaxf(mx1, __shfl_xor_sync(0xffffffffu, mx1, 2));
    float sum0 = 0.f, sum1 = 0.f;
#pragma unroll
    for (int nt = 0; nt < 8; nt++) {
#pragma unroll
        for (int e = 0; e < 2; e++) {
            float e0 = __expf(acc[nt][e] - mx0);
            float e1 = __expf(acc[nt][2 + e] - mx1);
            acc[nt][e] = e0; acc[nt][2 + e] = e1;
            sum0 += e0; sum1 += e1;
        }
    }
    sum0 += __shfl_xor_sync(0xffffffffu, sum0, 1);
    sum0 += __shfl_xor_sync(0xffffffffu, sum0, 2);
    sum1 += __shfl_xor_sync(0xffffffffu, sum1, 1);
    sum1 += __shfl_xor_sync(0xffffffffu, sum1, 2);
    float r0 = 1.f / sum0, r1 = 1.f / sum1;
#pragma unroll
    for (int nt = 0; nt < 8; nt++) {
        int j = nt * 8 + 2 * qc;
        ps[i0][j]     = acc[nt][0] * r0;
        ps[i0][j + 1] = acc[nt][1] * r0;
        ps[i1][j]     = acc[nt][2] * r1;
        ps[i1][j + 1] = acc[nt][3] * r1;
    }
    __syncwarp();

    // ---- ctx = P @ V : M=16, N=32, K=64 (4 n-tiles, 8 k-steps), split tf32 ----
    float o[4][4];
#pragma unroll
    for (int nt = 0; nt < 4; nt++)
#pragma unroll
        for (int t = 0; t < 4; t++) o[nt][t] = 0.f;

#pragma unroll
    for (int kt = 0; kt < 8; kt++) {
        int k0 = kt * 8;
        uint32_t ah[4], al[4];
        split_tf32(ps[i0][k0 + qc],     ah[0], al[0]);
        split_tf32(ps[i1][k0 + qc],     ah[1], al[1]);
        split_tf32(ps[i0][k0 + qc + 4], ah[2], al[2]);
        split_tf32(ps[i1][k0 + qc + 4], ah[3], al[3]);
#pragma unroll
        for (int nt = 0; nt < 4; nt++) {
            int d = nt * 8 + qr;
            uint32_t bh0, bl0, bh1, bl1;
            split_tf32(vs[k0 + qc][d],     bh0, bl0);
            split_tf32(vs[k0 + qc + 4][d], bh1, bl1);
            mma_tf32(o[nt][0], o[nt][1], o[nt][2], o[nt][3],
                     ah[0], ah[1], ah[2], ah[3], bh0, bh1);
            mma_tf32(o[nt][0], o[nt][1], o[nt][2], o[nt][3],
                     ah[0], ah[1], ah[2], ah[3], bl0, bl1);
            mma_tf32(o[nt][0], o[nt][1], o[nt][2], o[nt][3],
                     al[0], al[1], al[2], al[3], bh0, bh1);
        }
    }

    float* ob0 = g_ctx + ((long)(w * 64 + i0)) * CC + (hd << 5);
    float* ob1 = g_ctx + ((long)(w * 64 + i1)) * CC + (hd << 5);
#pragma unroll
    for (int nt = 0; nt < 4; nt++) {
        int d = nt * 8 + 2 * qc;
        *(float2*)(ob0 + d) = make_float2(o[nt][0], o[nt][1]);
        *(float2*)(ob1 + d) = make_float2(o[nt][2], o[nt][3]);
    }
}

// ======================= LayerNorm + residual =======================
__global__ void __launch_bounds__(256) k_ln_add(
    const float* __restrict__ xres, const float* __restrict__ xln,
    const float* __restrict__ g, const float* __restrict__ b,
    float* __restrict__ out) {
    int t = blockIdx.x * 8 + (threadIdx.x >> 5);
    int lane = threadIdx.x & 31;
    const float* row = xln + t * CC;
    float v[6];
    float sum = 0.f;
#pragma unroll
    for (int i = 0; i < 6; i++) { v[i] = row[lane + 32 * i]; sum += v[i]; }
#pragma unroll
    for (int o = 16; o > 0; o >>= 1) sum += __shfl_xor_sync(0xffffffffu, sum, o);
    float mu = sum * (1.0f / CC);
    float vs = 0.f;
#pragma unroll
    for (int i = 0; i < 6; i++) { float d = v[i] - mu; vs += d * d; }
#pragma unroll
    for (int o = 16; o > 0; o >>= 1) vs += __shfl_xor_sync(0xffffffffu, vs, o);
    float inv = rsqrtf(vs * (1.0f / CC) + 1e-5f);
#pragma unroll
    for (int i = 0; i < 6; i++) {
        int ch = lane + 32 * i;
        out[t * CC + ch] = xres[t * CC + ch] + (v[i] - mu) * inv * g[ch] + b[ch];
    }
}

// ======================= launch =======================
extern "C" void kernel_launch(void* const* d_in, const int* in_sizes, int n_in,
                              void* d_out, int out_size) {
    const float* hidden = (const float*)d_in[0];
    const float* q_w    = (const float*)d_in[1];
    const float* q_b    = (const float*)d_in[2];
    const float* k_w    = (const float*)d_in[3];
    const float* v_w    = (const float*)d_in[4];
    const float* v_b    = (const float*)d_in[5];
    const float* lscale = (const float*)d_in[6];
    const float* cpb_w1 = (const float*)d_in[7];
    const float* cpb_b1 = (const float*)d_in[8];
    const float* cpb_w2 = (const float*)d_in[9];
    const float* proj_w = (const float*)d_in[10];
    const float* proj_b = (const float*)d_in[11];
    const float* ln1_g  = (const float*)d_in[12];
    const float* ln1_b  = (const float*)d_in[13];
    const float* fc1_w  = (const float*)d_in[14];
    const float* fc1_b  = (const float*)d_in[15];
    const float* fc2_w  = (const float*)d_in[16];
    const float* fc2_b  = (const float*)d_in[17];
    const float* ln2_g  = (const float*)d_in[18];
    const float* ln2_b  = (const float*)d_in[19];
    float* out = (float*)d_out;

    float* gh; float* gxa; float* gmlp;
    cudaGetSymbolAddress((void**)&gh, g_h);
    cudaGetSymbolAddress((void**)&gxa, g_xattn);
    cudaGetSymbolAddress((void**)&gmlp, g_mlp);

    const int SMB = SMEM_FLOATS * 4;   // 92160 bytes
    cudaFuncSetAttribute(k_g<0>, cudaFuncAttributeMaxDynamicSharedMemorySize, SMB);
    cudaFuncSetAttribute(k_g<1>, cudaFuncAttributeMaxDynamicSharedMemorySize, SMB);
    cudaFuncSetAttribute(k_g<2>, cudaFuncAttributeMaxDynamicSharedMemorySize, SMB);
    cudaFuncSetAttribute(k_g<3>, cudaFuncAttributeMaxDynamicSharedMemorySize, SMB);

    k_tr<<<1152, 256>>>(q_w, k_w, v_w, proj_w, fc1_w, fc2_w);
    k_cpb<<<225, 512>>>(cpb_w1, cpb_b1, cpb_w2);
    k_rpb<<<(NHEADS * NTOK * NTOK + 255) / 256, 256>>>();
    k_g<0><<<dim3(1152, 3), 256, SMB>>>(hidden, q_b, v_b);
    k_attn<<<dim3(NWIN, NHEADS), 128>>>(lscale);
    k_g<1><<<dim3(1152, 1), 256, SMB>>>(nullptr, proj_b, nullptr);
    k_ln_add<<<TT / 8, 256>>>(hidden, gxa, ln1_g, ln1_b, gh);
    k_g<2><<<dim3(1152, 2), 256, SMB>>>(nullptr, fc1_b, nullptr);
    k_g<3><<<dim3(1152, 1), 256, SMB>>>(nullptr, fc2_b, nullptr);
    k_ln_add<<<TT / 8, 256>>>(gh, gmlp, ln2_g, ln2_b, out);
}